// round 8
// baseline (speedup 1.0000x reference)
#include <cuda_runtime.h>
#include <cstdint>

#define T_STEPS 512
#define HDIM    128
#define G4      512
#define OUTD    64
#define BSEL    255
#define SLICEF  36
#define HBUF    (4 * SLICEF)

__device__ float g_xg[T_STEPS * G4];
__device__ float g_hout[256 * HDIM];
__device__ float g_Wc[OUTD * HDIM];
__device__ float g_bc[OUTD];

__device__ __forceinline__ float fast_sigmoid(float x) {
    return 1.0f / (1.0f + __expf(-x));
}
__device__ __forceinline__ float fast_tanh(float x) {
    return 1.0f - 2.0f / (__expf(2.0f * x) + 1.0f);
}
__device__ __forceinline__ void fma_f32x2(unsigned long long& acc,
                                          unsigned long long a,
                                          unsigned long long b) {
    asm("fma.rn.f32x2 %0, %1, %2, %0;" : "+l"(acc) : "l"(a), "l"(b));
}
__device__ __forceinline__ unsigned long long add_f32x2(unsigned long long a,
                                                        unsigned long long b) {
    unsigned long long r;
    asm("add.rn.f32x2 %0, %1, %2;" : "=l"(r) : "l"(a), "l"(b));
    return r;
}
__device__ __forceinline__ uint32_t smem_u32(const void* p) {
    uint32_t a;
    asm("{ .reg .u64 t; cvta.to.shared.u64 t, %1; cvt.u32.u64 %0, t; }"
        : "=r"(a) : "l"(p));
    return a;
}
#define CLUSTER_SYNC() do { \
    asm volatile("barrier.cluster.arrive.aligned;" ::: "memory"); \
    asm volatile("barrier.cluster.wait.aligned;"   ::: "memory"); \
} while (0)

// ---------------- kernel 1: xg[t, j] = W_ih[j,:] . x[255,t,:] + b_ih + b_hh
__global__ void __launch_bounds__(512) xg_kernel(
    const float* __restrict__ x, const float* __restrict__ Wih,
    const float* __restrict__ bih, const float* __restrict__ bhh)
{
    __shared__ __align__(16) float xs[8][HDIM];
    int t0 = blockIdx.x * 8;
    int j  = threadIdx.x;

    for (int i = j; i < 8 * HDIM; i += 512) {
        int tt = i >> 7, d = i & 127;
        xs[tt][d] = x[((size_t)BSEL * T_STEPS + t0 + tt) * HDIM + d];
    }
    __syncthreads();

    const float4* wr4 = reinterpret_cast<const float4*>(Wih + j * HDIM);
    float acc[8];
    #pragma unroll
    for (int tt = 0; tt < 8; tt++) acc[tt] = 0.0f;

    #pragma unroll
    for (int q = 0; q < HDIM / 4; q++) {
        float4 w = wr4[q];
        #pragma unroll
        for (int tt = 0; tt < 8; tt++) {
            float4 xv = reinterpret_cast<const float4*>(xs[tt])[q];
            acc[tt] += w.x * xv.x + w.y * xv.y + w.z * xv.z + w.w * xv.w;
        }
    }
    float bb = bih[j] + bhh[j];
    #pragma unroll
    for (int tt = 0; tt < 8; tt++)
        g_xg[(t0 + tt) * G4 + j] = acc[tt] + bb;
}

// ---------------- kernel 2: collapse the two affine layers
__global__ void __launch_bounds__(512) mlp_precomp_kernel(
    const float* __restrict__ W1, const float* __restrict__ b1,
    const float* __restrict__ W2, const float* __restrict__ b2)
{
    int idx = blockIdx.x * blockDim.x + threadIdx.x;
    if (idx < OUTD * HDIM) {
        int o = idx >> 7, hh = idx & 127;
        float acc = 0.0f;
        #pragma unroll 4
        for (int m = 0; m < HDIM; m++)
            acc += W2[o * HDIM + m] * W1[m * HDIM + hh];
        g_Wc[idx] = acc;
    }
    if (idx < OUTD) {
        float acc = b2[idx];
        #pragma unroll 4
        for (int m = 0; m < HDIM; m++)
            acc += W2[idx * HDIM + m] * b1[m];
        g_bc[idx] = acc;
    }
}

// ---------------- kernel 3: sequential LSTM scan (batch 255 only)
// 2-CTA cluster, 512 threads each (R5 sync skeleton, double the warps).
//   eL = tid>>3, sub = tid&7, gp = sub&1 (gate pair {2gp,2gp+1}),
//   q = sub>>1 (global 32-col slice). 2 gates x 32 cols = 32 u64 weights,
//   32 FMA2/step in 4 chains, 8 LDS.128. Butterfly xor2+xor4 over q, one
//   xor1 swap for gate pairs. One CLUSTER_SYNC per step.
__global__ void __cluster_dims__(2, 1, 1) __launch_bounds__(512, 1)
lstm_scan_kernel(const float* __restrict__ Whh)
{
    __shared__ __align__(16) float h_smem[2 * HBUF];

    int tid = threadIdx.x;
    unsigned rank;
    asm("mov.u32 %0, %%cluster_ctarank;" : "=r"(rank));

    int sub = tid & 7;
    int eL  = tid >> 3;
    int gp  = sub & 1;
    int q   = sub >> 1;
    int e   = (int)rank * 64 + eL;

    // 2 gates x 16 u64 = 32 cols of weights per gate
    unsigned long long w2[2][16];
    #pragma unroll
    for (int gl = 0; gl < 2; gl++) {
        const unsigned long long* wsrc = reinterpret_cast<const unsigned long long*>(
            Whh + (size_t)((2 * gp + gl) * HDIM + e) * HDIM + q * 32);
        #pragma unroll
        for (int k = 0; k < 16; k++) w2[gl][k] = wsrc[k];
    }

    uint32_t hbase = smem_u32(h_smem);
    uint32_t rhbase;
    asm("mapa.shared::cluster.u32 %0, %1, %2;" : "=r"(rhbase) : "r"(hbase), "r"(rank ^ 1u));

    if (tid < HBUF) h_smem[tid] = 0.0f;
    __syncthreads();
    CLUSTER_SYNC();

    bool writer = (sub == 0);
    uint32_t woff = (uint32_t)(((e >> 5) * SLICEF + (e & 31)) * 4);

    float c = 0.0f;
    const float* xg_a = g_xg + (2 * gp) * HDIM + e;
    const float* xg_b = g_xg + (2 * gp + 1) * HDIM + e;

    for (int t = 0; t < T_STEPS; t++) {
        float xa = 0.0f, xb = 0.0f;
        if (q == 0) {
            xa = __ldg(xg_a + t * G4);
            xb = __ldg(xg_b + t * G4);
        }

        // 32 h floats of slice q: 8 LDS.128 -> 16 u64
        const ulonglong2* hp2 = reinterpret_cast<const ulonglong2*>(
            h_smem + (t & 1) * HBUF + q * SLICEF);
        unsigned long long hreg[16];
        #pragma unroll
        for (int k = 0; k < 8; k++) {
            ulonglong2 v = hp2[k];
            hreg[2 * k] = v.x;
            hreg[2 * k + 1] = v.y;
        }

        float p0, p1;
        {
            unsigned long long a0 = 0ull, a1 = 0ull, b0 = 0ull, b1 = 0ull;
            #pragma unroll
            for (int k = 0; k < 16; k += 2) {
                fma_f32x2(a0, w2[0][k],     hreg[k]);
                fma_f32x2(a1, w2[0][k + 1], hreg[k + 1]);
                fma_f32x2(b0, w2[1][k],     hreg[k]);
                fma_f32x2(b1, w2[1][k + 1], hreg[k + 1]);
            }
            unsigned long long sA = add_f32x2(a0, a1);
            unsigned long long sB = add_f32x2(b0, b1);
            float sx, sy;
            asm("mov.b64 {%0,%1}, %2;" : "=f"(sx), "=f"(sy) : "l"(sA));
            p0 = sx + sy;
            asm("mov.b64 {%0,%1}, %2;" : "=f"(sx), "=f"(sy) : "l"(sB));
            p1 = sx + sy;
        }
        p0 += xa;
        p1 += xb;

        p0 += __shfl_xor_sync(0xFFFFFFFFu, p0, 2);
        p1 += __shfl_xor_sync(0xFFFFFFFFu, p1, 2);
        p0 += __shfl_xor_sync(0xFFFFFFFFu, p0, 4);
        p1 += __shfl_xor_sync(0xFFFFFFFFu, p1, 4);

        float o0 = __shfl_xor_sync(0xFFFFFFFFu, p0, 1);
        float o1 = __shfl_xor_sync(0xFFFFFFFFu, p1, 1);
        float gi = (gp == 0) ? p0 : o0;
        float gf = (gp == 0) ? p1 : o1;
        float gg = (gp == 0) ? o0 : p0;
        float go = (gp == 0) ? o1 : p1;

        float iv = fast_sigmoid(gi);
        float fv = fast_sigmoid(gf);
        float gv = fast_tanh(gg);
        float ov = fast_sigmoid(go);
        c = fv * c + iv * gv;
        float h = ov * fast_tanh(c);

        if (writer) {
            uint32_t off = ((t + 1) & 1) * (HBUF * 4) + woff;
            asm volatile("st.shared.f32 [%0], %1;"
                         :: "r"(hbase + off), "f"(h) : "memory");
            asm volatile("st.shared::cluster.f32 [%0], %1;"
                         :: "r"(rhbase + off), "f"(h) : "memory");
            if (t >= 256) g_hout[(t - 256) * HDIM + e] = h;
        }
        CLUSTER_SYNC();
    }
}

// ---------------- kernel 4: out[j, o] = bc[o] + Wc[o,:] . h[255, 256+j, :]
__global__ void __launch_bounds__(64) mlp_final_kernel(float* __restrict__ out)
{
    __shared__ __align__(16) float hs[HDIM];
    int j = blockIdx.x;
    int o = threadIdx.x;
    hs[o]      = g_hout[j * HDIM + o];
    hs[o + 64] = g_hout[j * HDIM + 64 + o];
    __syncthreads();

    const float4* wr4 = reinterpret_cast<const float4*>(g_Wc + o * HDIM);
    float a0 = 0.0f, a1 = 0.0f;
    #pragma unroll
    for (int qq = 0; qq < HDIM / 4; qq += 2) {
        float4 w0 = wr4[qq],     x0 = reinterpret_cast<const float4*>(hs)[qq];
        float4 w1 = wr4[qq + 1], x1 = reinterpret_cast<const float4*>(hs)[qq + 1];
        a0 += w0.x * x0.x + w0.y * x0.y + w0.z * x0.z + w0.w * x0.w;
        a1 += w1.x * x1.x + w1.y * x1.y + w1.z * x1.z + w1.w * x1.w;
    }
    out[j * OUTD + o] = g_bc[o] + a0 + a1;
}

extern "C" void kernel_launch(void* const* d_in, const int* in_sizes, int n_in,
                              void* d_out, int out_size)
{
    const float* x   = (const float*)d_in[0];
    const float* Wih = (const float*)d_in[1];
    const float* Whh = (const float*)d_in[2];
    const float* bih = (const float*)d_in[3];
    const float* bhh = (const float*)d_in[4];
    const float* W1  = (const float*)d_in[5];
    const float* b1  = (const float*)d_in[6];
    const float* W2  = (const float*)d_in[7];
    const float* b2  = (const float*)d_in[8];
    float* out = (float*)d_out;

    xg_kernel<<<64, 512>>>(x, Wih, bih, bhh);
    mlp_precomp_kernel<<<16, 512>>>(W1, b1, W2, b2);
    lstm_scan_kernel<<<2, 512>>>(Whh);
    mlp_final_kernel<<<256, 64>>>(out);
}

// round 10
// speedup vs baseline: 1.5888x; 1.5888x over previous
#include <cuda_runtime.h>
#include <cstdint>

// Problem constants
#define T_STEPS 512
#define HDIM    128
#define G4      512     // 4*H
#define OUTD    64
#define BSEL    255     // only batch row that affects the output
#define SLICEF  36      // 32 floats + 4 pad per column-slice (bank shift)
#define HBUF    (4 * SLICEF)   // one h buffer = 144 floats

// ---------------- scratch (no allocations allowed) ----------------
__device__ float g_xg[T_STEPS * G4];     // precomputed input gates for batch 255
__device__ float g_hout[256 * HDIM];     // h[255, 256+j, :]
__device__ float g_Wc[OUTD * HDIM];      // W2 @ W1
__device__ float g_bc[OUTD];             // W2 @ b1 + b2

// ---------------- helpers ----------------
__device__ __forceinline__ float tanh_mufu(float x) {
    float y;
    asm("tanh.approx.f32 %0, %1;" : "=f"(y) : "f"(x));
    return y;
}
__device__ __forceinline__ float sigmoid_mufu(float x) {
    // sigmoid(x) = 0.5*tanh(0.5x) + 0.5  (halves the approx error too)
    return fmaf(0.5f, tanh_mufu(0.5f * x), 0.5f);
}
__device__ __forceinline__ void fma_f32x2(unsigned long long& acc,
                                          unsigned long long a,
                                          unsigned long long b) {
    asm("fma.rn.f32x2 %0, %1, %2, %0;" : "+l"(acc) : "l"(a), "l"(b));
}
__device__ __forceinline__ unsigned long long add_f32x2(unsigned long long a,
                                                        unsigned long long b) {
    unsigned long long r;
    asm("add.rn.f32x2 %0, %1, %2;" : "=l"(r) : "l"(a), "l"(b));
    return r;
}
__device__ __forceinline__ uint32_t smem_u32(const void* p) {
    uint32_t a;
    asm("{ .reg .u64 t; cvta.to.shared.u64 t, %1; cvt.u32.u64 %0, t; }"
        : "=r"(a) : "l"(p));
    return a;
}
#define CLUSTER_SYNC() do { \
    asm volatile("barrier.cluster.arrive.aligned;" ::: "memory"); \
    asm volatile("barrier.cluster.wait.aligned;"   ::: "memory"); \
} while (0)
#define CLUSTER_ARRIVE() asm volatile("barrier.cluster.arrive.aligned;" ::: "memory")
#define CLUSTER_WAIT()   asm volatile("barrier.cluster.wait.aligned;"   ::: "memory")

// ---------------- kernel 1: xg[t, j] = W_ih[j,:] . x[255,t,:] + b_ih + b_hh
__global__ void __launch_bounds__(512) xg_kernel(
    const float* __restrict__ x, const float* __restrict__ Wih,
    const float* __restrict__ bih, const float* __restrict__ bhh)
{
    __shared__ __align__(16) float xs[8][HDIM];
    int t0 = blockIdx.x * 8;
    int j  = threadIdx.x;

    for (int i = j; i < 8 * HDIM; i += 512) {
        int tt = i >> 7, d = i & 127;
        xs[tt][d] = x[((size_t)BSEL * T_STEPS + t0 + tt) * HDIM + d];
    }
    __syncthreads();

    const float4* wr4 = reinterpret_cast<const float4*>(Wih + j * HDIM);
    float acc[8];
    #pragma unroll
    for (int tt = 0; tt < 8; tt++) acc[tt] = 0.0f;

    #pragma unroll
    for (int q = 0; q < HDIM / 4; q++) {
        float4 w = wr4[q];
        #pragma unroll
        for (int tt = 0; tt < 8; tt++) {
            float4 xv = reinterpret_cast<const float4*>(xs[tt])[q];
            acc[tt] += w.x * xv.x + w.y * xv.y + w.z * xv.z + w.w * xv.w;
        }
    }
    float bb = bih[j] + bhh[j];
    #pragma unroll
    for (int tt = 0; tt < 8; tt++)
        g_xg[(t0 + tt) * G4 + j] = acc[tt] + bb;
}

// ---------------- kernel 2: collapse the two affine layers
__global__ void __launch_bounds__(512) mlp_precomp_kernel(
    const float* __restrict__ W1, const float* __restrict__ b1,
    const float* __restrict__ W2, const float* __restrict__ b2)
{
    int idx = blockIdx.x * blockDim.x + threadIdx.x;
    if (idx < OUTD * HDIM) {
        int o = idx >> 7, hh = idx & 127;
        float acc = 0.0f;
        #pragma unroll 4
        for (int m = 0; m < HDIM; m++)
            acc += W2[o * HDIM + m] * W1[m * HDIM + hh];
        g_Wc[idx] = acc;
    }
    if (idx < OUTD) {
        float acc = b2[idx];
        #pragma unroll 4
        for (int m = 0; m < HDIM; m++)
            acc += W2[idx * HDIM + m] * b1[m];
        g_bc[idx] = acc;
    }
}

// ---------------- kernel 3: sequential LSTM scan (batch 255 only)
// R5 architecture (measured best): 2-CTA cluster, 256 threads each,
//   q = tid&3 -> 32-col slice, eL = tid>>2 -> element, R=4 reuse of h regs,
//   butterfly xor1+xor2, one cluster barrier per step, double-buffered h.
// R10 deltas: MUFU tanh.approx gates; split barrier arrive/wait with the
//   g_hout store + next-step xg prefetch hidden in the gap.
__global__ void __cluster_dims__(2, 1, 1) __launch_bounds__(256, 1)
lstm_scan_kernel(const float* __restrict__ Whh)
{
    __shared__ __align__(16) float h_smem[2 * HBUF];

    int tid = threadIdx.x;
    unsigned rank;
    asm("mov.u32 %0, %%cluster_ctarank;" : "=r"(rank));

    int q  = tid & 3;
    int eL = tid >> 2;
    int e  = (int)rank * 64 + eL;          // global hidden element

    // register-resident weights: w2[g][k] covers gate g, cols [q*32+2k, +2)
    unsigned long long w2[4][16];
    #pragma unroll
    for (int g = 0; g < 4; g++) {
        const unsigned long long* wsrc = reinterpret_cast<const unsigned long long*>(
            Whh + (size_t)(g * HDIM + e) * HDIM + q * 32);
        #pragma unroll
        for (int k = 0; k < 16; k++) w2[g][k] = wsrc[k];
    }

    uint32_t hbase = smem_u32(h_smem);
    uint32_t rhbase;
    asm("mapa.shared::cluster.u32 %0, %1, %2;" : "=r"(rhbase) : "r"(hbase), "r"(rank ^ 1u));

    // zero buffer 0 (input of step 0)
    if (tid < HBUF) h_smem[tid] = 0.0f;
    __syncthreads();
    CLUSTER_SYNC();

    bool writer = (q == 0);
    // writer's padded slot for element e in an h buffer (slice e>>5, pos e&31)
    uint32_t woff = (uint32_t)(((e >> 5) * SLICEF + (e & 31)) * 4);

    float c = 0.0f;                        // redundant across the 4 lanes
    const float* xg_base = g_xg + q * HDIM + e;   // row (gate q, element e)

    // software-pipelined xg: load step 0's value up front
    float xgv = __ldg(xg_base);

    for (int t = 0; t < T_STEPS; t++) {
        // load this thread's 32 h floats once (slice q of current buffer)
        const ulonglong2* hp2 = reinterpret_cast<const ulonglong2*>(
            h_smem + (t & 1) * HBUF + q * SLICEF);
        unsigned long long hreg[16];
        #pragma unroll
        for (int k = 0; k < 8; k++) {
            ulonglong2 v = hp2[k];
            hreg[2 * k] = v.x;
            hreg[2 * k + 1] = v.y;
        }

        // 4 gate partial dots over the 32-col slice (reusing hreg)
        float p[4];
        #pragma unroll
        for (int g = 0; g < 4; g++) {
            unsigned long long a0 = 0ull, a1 = 0ull;
            #pragma unroll
            for (int k = 0; k < 16; k += 2) {
                fma_f32x2(a0, w2[g][k],     hreg[k]);
                fma_f32x2(a1, w2[g][k + 1], hreg[k + 1]);
            }
            unsigned long long s = add_f32x2(a0, a1);
            float sx, sy;
            asm("mov.b64 {%0,%1}, %2;" : "=f"(sx), "=f"(sy) : "l"(s));
            p[g] = sx + sy;
        }
        p[q] += xgv;   // each gate's xg added exactly once across the group

        // butterfly-reduce the 4-lane group: all lanes end with full gate sums
        #pragma unroll
        for (int g = 0; g < 4; g++) p[g] += __shfl_xor_sync(0xFFFFFFFFu, p[g], 1);
        #pragma unroll
        for (int g = 0; g < 4; g++) p[g] += __shfl_xor_sync(0xFFFFFFFFu, p[g], 2);

        // gate math via MUFU.TANH (redundant in all 4 lanes, no divergence)
        float iv = sigmoid_mufu(p[0]);
        float fv = sigmoid_mufu(p[1]);
        float gv = tanh_mufu(p[2]);
        float ov = sigmoid_mufu(p[3]);
        c = fv * c + iv * gv;
        float h = ov * tanh_mufu(c);

        if (writer) {
            uint32_t off = ((t + 1) & 1) * (HBUF * 4) + woff;
            asm volatile("st.shared.f32 [%0], %1;"
                         :: "r"(hbase + off), "f"(h) : "memory");
            asm volatile("st.shared::cluster.f32 [%0], %1;"
                         :: "r"(rhbase + off), "f"(h) : "memory");
        }

        // split barrier: arrive now, hide gmem traffic in the gap, wait last
        CLUSTER_ARRIVE();

        if (writer && t >= 256) g_hout[(t - 256) * HDIM + e] = h;
        int tn = (t + 1 < T_STEPS) ? (t + 1) : t;      // clamped prefetch index
        xgv = __ldg(xg_base + tn * G4);

        CLUSTER_WAIT();
    }
}

// ---------------- kernel 4: out[j, o] = bc[o] + Wc[o,:] . h[255, 256+j, :]
__global__ void __launch_bounds__(64) mlp_final_kernel(float* __restrict__ out)
{
    __shared__ __align__(16) float hs[HDIM];
    int j = blockIdx.x;
    int o = threadIdx.x;
    hs[o]      = g_hout[j * HDIM + o];
    hs[o + 64] = g_hout[j * HDIM + 64 + o];
    __syncthreads();

    const float4* wr4 = reinterpret_cast<const float4*>(g_Wc + o * HDIM);
    float a0 = 0.0f, a1 = 0.0f;
    #pragma unroll
    for (int qq = 0; qq < HDIM / 4; qq += 2) {
        float4 w0 = wr4[qq],     v0 = reinterpret_cast<const float4*>(hs)[qq];
        float4 w1 = wr4[qq + 1], v1 = reinterpret_cast<const float4*>(hs)[qq + 1];
        a0 += w0.x * v0.x + w0.y * v0.y + w0.z * v0.z + w0.w * v0.w;
        a1 += w1.x * v1.x + w1.y * v1.y + w1.z * v1.z + w1.w * v1.w;
    }
    out[j * OUTD + o] = g_bc[o] + a0 + a1;
}

// ---------------- launch ----------------
extern "C" void kernel_launch(void* const* d_in, const int* in_sizes, int n_in,
                              void* d_out, int out_size)
{
    const float* x   = (const float*)d_in[0];
    const float* Wih = (const float*)d_in[1];
    const float* Whh = (const float*)d_in[2];
    const float* bih = (const float*)d_in[3];
    const float* bhh = (const float*)d_in[4];
    const float* W1  = (const float*)d_in[5];
    const float* b1  = (const float*)d_in[6];
    const float* W2  = (const float*)d_in[7];
    const float* b2  = (const float*)d_in[8];
    float* out = (float*)d_out;

    xg_kernel<<<64, 512>>>(x, Wih, bih, bhh);
    mlp_precomp_kernel<<<16, 512>>>(W1, b1, W2, b2);
    lstm_scan_kernel<<<2, 256>>>(Whh);
    mlp_final_kernel<<<256, 64>>>(out);
}

// round 11
// speedup vs baseline: 1.8035x; 1.1351x over previous
#include <cuda_runtime.h>
#include <cstdint>

// Problem constants
#define T_STEPS 512
#define HDIM    128
#define G4      512     // 4*H
#define OUTD    64
#define BSEL    255     // only batch row that affects the output
#define SLICEF  36      // 32 floats + 4 pad per column-slice (bank shift)
#define HBUF    (4 * SLICEF)   // one h buffer = 144 floats (all 128 elements)
#define NCTA    4

// ---------------- scratch (no allocations allowed) ----------------
__device__ float g_xg[T_STEPS * G4];     // precomputed input gates for batch 255
__device__ float g_hout[256 * HDIM];     // h[255, 256+j, :]
__device__ float g_Wc[OUTD * HDIM];      // W2 @ W1
__device__ float g_bc[OUTD];             // W2 @ b1 + b2

// ---------------- helpers ----------------
__device__ __forceinline__ float tanh_mufu(float x) {
    float y;
    asm("tanh.approx.f32 %0, %1;" : "=f"(y) : "f"(x));
    return y;
}
__device__ __forceinline__ float sigmoid_mufu(float x) {
    return fmaf(0.5f, tanh_mufu(0.5f * x), 0.5f);
}
__device__ __forceinline__ void fma_f32x2(unsigned long long& acc,
                                          unsigned long long a,
                                          unsigned long long b) {
    asm("fma.rn.f32x2 %0, %1, %2, %0;" : "+l"(acc) : "l"(a), "l"(b));
}
__device__ __forceinline__ unsigned long long add_f32x2(unsigned long long a,
                                                        unsigned long long b) {
    unsigned long long r;
    asm("add.rn.f32x2 %0, %1, %2;" : "=l"(r) : "l"(a), "l"(b));
    return r;
}
__device__ __forceinline__ uint32_t smem_u32(const void* p) {
    uint32_t a;
    asm("{ .reg .u64 t; cvta.to.shared.u64 t, %1; cvt.u32.u64 %0, t; }"
        : "=r"(a) : "l"(p));
    return a;
}
#define CLUSTER_SYNC() do { \
    asm volatile("barrier.cluster.arrive.aligned;" ::: "memory"); \
    asm volatile("barrier.cluster.wait.aligned;"   ::: "memory"); \
} while (0)
#define CLUSTER_ARRIVE() asm volatile("barrier.cluster.arrive.aligned;" ::: "memory")
#define CLUSTER_WAIT()   asm volatile("barrier.cluster.wait.aligned;"   ::: "memory")

// ---------------- kernel 1: xg[t, j] = W_ih[j,:] . x[255,t,:] + b_ih + b_hh
__global__ void __launch_bounds__(512) xg_kernel(
    const float* __restrict__ x, const float* __restrict__ Wih,
    const float* __restrict__ bih, const float* __restrict__ bhh)
{
    __shared__ __align__(16) float xs[8][HDIM];
    int t0 = blockIdx.x * 8;
    int j  = threadIdx.x;

    for (int i = j; i < 8 * HDIM; i += 512) {
        int tt = i >> 7, d = i & 127;
        xs[tt][d] = x[((size_t)BSEL * T_STEPS + t0 + tt) * HDIM + d];
    }
    __syncthreads();

    const float4* wr4 = reinterpret_cast<const float4*>(Wih + j * HDIM);
    float acc[8];
    #pragma unroll
    for (int tt = 0; tt < 8; tt++) acc[tt] = 0.0f;

    #pragma unroll
    for (int q = 0; q < HDIM / 4; q++) {
        float4 w = wr4[q];
        #pragma unroll
        for (int tt = 0; tt < 8; tt++) {
            float4 xv = reinterpret_cast<const float4*>(xs[tt])[q];
            acc[tt] += w.x * xv.x + w.y * xv.y + w.z * xv.z + w.w * xv.w;
        }
    }
    float bb = bih[j] + bhh[j];
    #pragma unroll
    for (int tt = 0; tt < 8; tt++)
        g_xg[(t0 + tt) * G4 + j] = acc[tt] + bb;
}

// ---------------- kernel 2: collapse the two affine layers
__global__ void __launch_bounds__(512) mlp_precomp_kernel(
    const float* __restrict__ W1, const float* __restrict__ b1,
    const float* __restrict__ W2, const float* __restrict__ b2)
{
    int idx = blockIdx.x * blockDim.x + threadIdx.x;
    if (idx < OUTD * HDIM) {
        int o = idx >> 7, hh = idx & 127;
        float acc = 0.0f;
        #pragma unroll 4
        for (int m = 0; m < HDIM; m++)
            acc += W2[o * HDIM + m] * W1[m * HDIM + hh];
        g_Wc[idx] = acc;
    }
    if (idx < OUTD) {
        float acc = b2[idx];
        #pragma unroll 4
        for (int m = 0; m < HDIM; m++)
            acc += W2[idx * HDIM + m] * b1[m];
        g_bc[idx] = acc;
    }
}

// ---------------- kernel 3: sequential LSTM scan (batch 255 only)
// 4-CTA cluster, 256 threads each -> 2x the SMs of R10, FMA2 issue halved.
// Thread tid: eL = tid>>3 (this CTA's 32 elements), sub = tid&7:
//   gp = sub&1 (gate pair {2gp, 2gp+1}), q = sub>>2? NO: q = sub>>1 (slice).
//   Each thread: 2 gate rows x 32 cols = 32 reg-resident u64 weights,
//   32 FMA2/step, 8 LDS.128. Butterfly xor2+xor4 over slices, xor1 swap for
//   gate pairs (validated R8 pattern). MUFU gates (validated R10).
// Writers (sub==0): store h locally + to all 3 peer CTAs (st.shared::cluster).
// One split CLUSTER_SYNC per step with g_hout + xg prefetch in the gap (R10).
__global__ void __cluster_dims__(NCTA, 1, 1) __launch_bounds__(256, 1)
lstm_scan_kernel(const float* __restrict__ Whh)
{
    __shared__ __align__(16) float h_smem[2 * HBUF];

    int tid = threadIdx.x;
    unsigned rank;
    asm("mov.u32 %0, %%cluster_ctarank;" : "=r"(rank));

    int sub = tid & 7;
    int eL  = tid >> 3;            // 0..31
    int gp  = sub & 1;
    int q   = sub >> 1;            // 0..3, 32-col slice
    int e   = (int)rank * 32 + eL; // global hidden element

    // register-resident weights: 2 gates x 16 u64 (cols q*32 .. q*32+31)
    unsigned long long w2[2][16];
    #pragma unroll
    for (int gl = 0; gl < 2; gl++) {
        const unsigned long long* wsrc = reinterpret_cast<const unsigned long long*>(
            Whh + (size_t)((2 * gp + gl) * HDIM + e) * HDIM + q * 32);
        #pragma unroll
        for (int k = 0; k < 16; k++) w2[gl][k] = wsrc[k];
    }

    uint32_t hbase = smem_u32(h_smem);
    uint32_t rh[3];                 // peer CTA h bases
    #pragma unroll
    for (int r = 1; r < NCTA; r++) {
        unsigned peer = (rank + (unsigned)r) & (NCTA - 1);
        asm("mapa.shared::cluster.u32 %0, %1, %2;"
            : "=r"(rh[r - 1]) : "r"(hbase), "r"(peer));
    }

    // zero both h buffers (t=0 input must be zero everywhere)
    for (int i = tid; i < 2 * HBUF; i += 256) h_smem[i] = 0.0f;
    __syncthreads();
    CLUSTER_SYNC();

    bool writer = (sub == 0);
    // padded slot of element e in an h buffer (slice e>>5, pos e&31)
    uint32_t woff = (uint32_t)(((e >> 5) * SLICEF + (e & 31)) * 4);

    float c = 0.0f;                 // identical across the 8 lanes of the group
    const float* xg_a = g_xg + (2 * gp) * HDIM + e;
    const float* xg_b = g_xg + (2 * gp + 1) * HDIM + e;

    // software-pipelined xg (only q==0 lanes contribute)
    float xa = 0.0f, xb = 0.0f;
    if (q == 0) { xa = __ldg(xg_a); xb = __ldg(xg_b); }

    for (int t = 0; t < T_STEPS; t++) {
        // 32 h floats of slice q: 8 LDS.128 -> 16 u64
        const ulonglong2* hp2 = reinterpret_cast<const ulonglong2*>(
            h_smem + (t & 1) * HBUF + q * SLICEF);
        unsigned long long hreg[16];
        #pragma unroll
        for (int k = 0; k < 8; k++) {
            ulonglong2 v = hp2[k];
            hreg[2 * k] = v.x;
            hreg[2 * k + 1] = v.y;
        }

        // 2 gate partial dots over the 32-col slice
        float p0, p1;
        {
            unsigned long long a0 = 0ull, a1 = 0ull, b0 = 0ull, b1 = 0ull;
            #pragma unroll
            for (int k = 0; k < 16; k += 2) {
                fma_f32x2(a0, w2[0][k],     hreg[k]);
                fma_f32x2(a1, w2[0][k + 1], hreg[k + 1]);
                fma_f32x2(b0, w2[1][k],     hreg[k]);
                fma_f32x2(b1, w2[1][k + 1], hreg[k + 1]);
            }
            unsigned long long sA = add_f32x2(a0, a1);
            unsigned long long sB = add_f32x2(b0, b1);
            float sx, sy;
            asm("mov.b64 {%0,%1}, %2;" : "=f"(sx), "=f"(sy) : "l"(sA));
            p0 = sx + sy;
            asm("mov.b64 {%0,%1}, %2;" : "=f"(sx), "=f"(sy) : "l"(sB));
            p1 = sx + sy;
        }
        p0 += xa;
        p1 += xb;

        // sum over the 4 slices (lane bits 1..2), then swap gate pairs (bit 0)
        p0 += __shfl_xor_sync(0xFFFFFFFFu, p0, 2);
        p1 += __shfl_xor_sync(0xFFFFFFFFu, p1, 2);
        p0 += __shfl_xor_sync(0xFFFFFFFFu, p0, 4);
        p1 += __shfl_xor_sync(0xFFFFFFFFu, p1, 4);
        float o0 = __shfl_xor_sync(0xFFFFFFFFu, p0, 1);
        float o1 = __shfl_xor_sync(0xFFFFFFFFu, p1, 1);
        float gi = (gp == 0) ? p0 : o0;
        float gf = (gp == 0) ? p1 : o1;
        float gg = (gp == 0) ? o0 : p0;
        float go = (gp == 0) ? o1 : p1;

        // gate math via MUFU.TANH (redundant in all 8 lanes, no divergence)
        float iv = sigmoid_mufu(gi);
        float fv = sigmoid_mufu(gf);
        float gv = tanh_mufu(gg);
        float ov = sigmoid_mufu(go);
        c = fv * c + iv * gv;
        float h = ov * tanh_mufu(c);

        if (writer) {
            uint32_t off = ((t + 1) & 1) * (HBUF * 4) + woff;
            asm volatile("st.shared.f32 [%0], %1;"
                         :: "r"(hbase + off), "f"(h) : "memory");
            #pragma unroll
            for (int r = 0; r < NCTA - 1; r++)
                asm volatile("st.shared::cluster.f32 [%0], %1;"
                             :: "r"(rh[r] + off), "f"(h) : "memory");
        }

        // split barrier: arrive now, hide gmem traffic, wait last
        CLUSTER_ARRIVE();

        if (writer && t >= 256) g_hout[(t - 256) * HDIM + e] = h;
        int tn = (t + 1 < T_STEPS) ? (t + 1) : t;
        if (q == 0) {
            xa = __ldg(xg_a + tn * G4);
            xb = __ldg(xg_b + tn * G4);
        }

        CLUSTER_WAIT();
    }
}

// ---------------- kernel 4: out[j, o] = bc[o] + Wc[o,:] . h[255, 256+j, :]
__global__ void __launch_bounds__(64) mlp_final_kernel(float* __restrict__ out)
{
    __shared__ __align__(16) float hs[HDIM];
    int j = blockIdx.x;
    int o = threadIdx.x;
    hs[o]      = g_hout[j * HDIM + o];
    hs[o + 64] = g_hout[j * HDIM + 64 + o];
    __syncthreads();

    const float4* wr4 = reinterpret_cast<const float4*>(g_Wc + o * HDIM);
    float a0 = 0.0f, a1 = 0.0f;
    #pragma unroll
    for (int qq = 0; qq < HDIM / 4; qq += 2) {
        float4 w0 = wr4[qq],     v0 = reinterpret_cast<const float4*>(hs)[qq];
        float4 w1 = wr4[qq + 1], v1 = reinterpret_cast<const float4*>(hs)[qq + 1];
        a0 += w0.x * v0.x + w0.y * v0.y + w0.z * v0.z + w0.w * v0.w;
        a1 += w1.x * v1.x + w1.y * v1.y + w1.z * v1.z + w1.w * v1.w;
    }
    out[j * OUTD + o] = g_bc[o] + a0 + a1;
}

// ---------------- launch ----------------
extern "C" void kernel_launch(void* const* d_in, const int* in_sizes, int n_in,
                              void* d_out, int out_size)
{
    const float* x   = (const float*)d_in[0];
    const float* Wih = (const float*)d_in[1];
    const float* Whh = (const float*)d_in[2];
    const float* bih = (const float*)d_in[3];
    const float* bhh = (const float*)d_in[4];
    const float* W1  = (const float*)d_in[5];
    const float* b1  = (const float*)d_in[6];
    const float* W2  = (const float*)d_in[7];
    const float* b2  = (const float*)d_in[8];
    float* out = (float*)d_out;

    xg_kernel<<<64, 512>>>(x, Wih, bih, bhh);
    mlp_precomp_kernel<<<16, 512>>>(W1, b1, W2, b2);
    lstm_scan_kernel<<<NCTA, 256>>>(Whh);
    mlp_final_kernel<<<256, 64>>>(out);
}